// round 3
// baseline (speedup 1.0000x reference)
#include <cuda_runtime.h>

// ---------------------------------------------------------------------------
// GCN layer (push-mode segment mean + tiny per-node MLPs)
// R3: edge phase split into 2 launches (ncu visibility), 8 edges/thread.
// ---------------------------------------------------------------------------

#define NODE_CAP 1048576  // N = 1e6 in this problem

// Scratch: xyz = neighbor-feature sum, w = degree
__device__ float4 g_accum[NODE_CAP];
// Repacked features: xyz = feature, w = 1.0
__device__ float4 g_feat[NODE_CAP];

__global__ void prep_kernel(const float* __restrict__ feat, int n) {
    int i = blockIdx.x * blockDim.x + threadIdx.x;
    if (i < n) {
        g_accum[i] = make_float4(0.f, 0.f, 0.f, 0.f);
        g_feat[i]  = make_float4(feat[3 * i], feat[3 * i + 1], feat[3 * i + 2], 1.0f);
    }
}

__device__ __forceinline__ void edge_op(int s, int d) {
    float4 f = __ldg(&g_feat[s]);
    float4* p = g_accum + d;
    asm volatile("red.global.add.v4.f32 [%0], {%1, %2, %3, %4};"
                 :: "l"(p), "f"(f.x), "f"(f.y), "f"(f.z), "f"(f.w) : "memory");
}

// Processes edges [base, base+count). base and count are multiples of 8
// except possibly the final launch, which handles the tail scalar-wise.
__global__ void edge_kernel(const int* __restrict__ src,
                            const int* __restrict__ dst,
                            long long base, long long count) {
    long long i8 = (long long)(blockIdx.x) * blockDim.x + threadIdx.x;
    long long e8 = count / 8;
    if (i8 < e8) {
        long long e = base + i8 * 8;
        const int4* s4 = reinterpret_cast<const int4*>(src + e);
        const int4* d4 = reinterpret_cast<const int4*>(dst + e);
        int4 sA = __ldcg(s4);     int4 dA = __ldcg(d4);
        int4 sB = __ldcg(s4 + 1); int4 dB = __ldcg(d4 + 1);
        edge_op(sA.x, dA.x); edge_op(sA.y, dA.y);
        edge_op(sA.z, dA.z); edge_op(sA.w, dA.w);
        edge_op(sB.x, dB.x); edge_op(sB.y, dB.y);
        edge_op(sB.z, dB.z); edge_op(sB.w, dB.w);
    } else if (i8 == e8) {
        // tail (count % 8 edges)
        long long e = base + e8 * 8;
        long long end = base + count;
        for (; e < end; e++) edge_op(src[e], dst[e]);
    }
}

__global__ void node_kernel(const float* __restrict__ x_attr,
                            const float* __restrict__ label,
                            const float* __restrict__ W0, const float* __restrict__ b0,
                            const float* __restrict__ W1, const float* __restrict__ b1,
                            const float* __restrict__ W2, const float* __restrict__ b2,
                            const float* __restrict__ Wa, const float* __restrict__ ba,
                            float* __restrict__ out, int n) {
    __shared__ float sW0[3], sW1[9], sW2[6], sWa[27], sB[3], sBa[3];
    int t = threadIdx.x;
    if (t < 3)  { sW0[t] = W0[t]; sB[t] = b0[t] + b1[t] + b2[t]; sBa[t] = ba[t]; }
    if (t < 9)  sW1[t] = W1[t];
    if (t < 6)  sW2[t] = W2[t];
    if (t < 27) sWa[t] = Wa[t];
    __syncthreads();

    int i = blockIdx.x * blockDim.x + threadIdx.x;
    if (i >= n) return;

    float4 acc = g_accum[i];
    float inv = 1.0f / fmaxf(acc.w, 1.0f);
    float hg0 = acc.x * inv, hg1 = acc.y * inv, hg2 = acc.z * inv;

    float4 f4 = g_feat[i];
    float f0 = f4.x, f1 = f4.y, f2 = f4.z;
    float x0 = x_attr[2 * i], x1 = x_attr[2 * i + 1];
    float lb = label[i];

    float a[3];
#pragma unroll
    for (int j = 0; j < 3; j++) {
        float v = lb * sW0[j]
                + hg0 * sW1[0 * 3 + j] + hg1 * sW1[1 * 3 + j] + hg2 * sW1[2 * 3 + j]
                + x0 * sW2[0 * 3 + j] + x1 * sW2[1 * 3 + j]
                + sB[j];
        a[j] = fmaxf(v, 0.f);
    }

#pragma unroll
    for (int j = 0; j < 3; j++) {
        float v = a[0] * sWa[0 * 3 + j] + a[1] * sWa[1 * 3 + j] + a[2] * sWa[2 * 3 + j]
                + hg0 * sWa[3 * 3 + j] + hg1 * sWa[4 * 3 + j] + hg2 * sWa[5 * 3 + j]
                + f0 * sWa[6 * 3 + j] + f1 * sWa[7 * 3 + j] + f2 * sWa[8 * 3 + j]
                + sBa[j];
        out[3 * i + j] = fmaxf(v, 0.f);
    }
}

extern "C" void kernel_launch(void* const* d_in, const int* in_sizes, int n_in,
                              void* d_out, int out_size) {
    const float* feature = (const float*)d_in[0];
    const float* x_attr  = (const float*)d_in[1];
    const float* label   = (const float*)d_in[2];
    const float* W0 = (const float*)d_in[3];
    const float* b0 = (const float*)d_in[4];
    const float* W1 = (const float*)d_in[5];
    const float* b1 = (const float*)d_in[6];
    const float* W2 = (const float*)d_in[7];
    const float* b2 = (const float*)d_in[8];
    const float* Wa = (const float*)d_in[9];
    const float* ba = (const float*)d_in[10];
    const int*   src = (const int*)d_in[11];
    const int*   dst = (const int*)d_in[12];
    float* out = (float*)d_out;

    int N = in_sizes[0] / 3;
    long long E = in_sizes[11];

    const int TB = 256;
    prep_kernel<<<(N + TB - 1) / TB, TB>>>(feature, N);

    // Split edge work into two launches (halves aligned to 8 edges).
    long long half = ((E / 2) / 8) * 8;
    long long cntA = half, cntB = E - half;
    long long thrA = cntA / 8 + 1, thrB = cntB / 8 + 1;
    edge_kernel<<<(unsigned)((thrA + TB - 1) / TB), TB>>>(src, dst, 0, cntA);
    edge_kernel<<<(unsigned)((thrB + TB - 1) / TB), TB>>>(src, dst, half, cntB);

    node_kernel<<<(N + TB - 1) / TB, TB>>>(x_attr, label,
                                           W0, b0, W1, b1, W2, b2, Wa, ba,
                                           out, N);
}